// round 1
// baseline (speedup 1.0000x reference)
#include <cuda_runtime.h>
#include <math.h>

#define Bz  8
#define Tz  512
#define Hz  768
#define NHz 12
#define HDz 64
#define FFz 3072
#define Lz  12
#define Mz  (Bz*Tz)   // 4096

// ---------------- scratch (no allocation allowed) ----------------
__device__ float g_q[Mz*Hz];
__device__ float g_k[Mz*Hz];
__device__ float g_v[Mz*Hz];
__device__ float g_ctx[Mz*Hz];
__device__ float g_proj[Mz*Hz];
__device__ float g_attn[Mz*Hz];
__device__ float g_x[Mz*Hz];
__device__ float g_ff[Mz*FFz];

// ---------------- GEMM: C[M,N] = A[M,K] @ B[K,N] + bias (+GELU) ----------------
// 64x64 tile, BK=16, 16x16 threads, 4x4 per-thread register tile, strided mapping.
template<bool GELU>
__global__ __launch_bounds__(256) void gemm_bias_kernel(
    const float* __restrict__ A, const float* __restrict__ B,
    const float* __restrict__ bias, float* __restrict__ C,
    int M, int N, int K)
{
    __shared__ float As[16][65];
    __shared__ float Bs[16][65];
    const int tx = threadIdx.x, ty = threadIdx.y;
    const int tid = ty * 16 + tx;
    const int m0 = blockIdx.y * 64, n0 = blockIdx.x * 64;

    const int a_m  = tid >> 2;          // 0..63
    const int a_k4 = (tid & 3) * 4;     // 0,4,8,12
    const int b_k  = tid >> 4;          // 0..15
    const int b_n4 = (tid & 15) * 4;    // 0..60

    const float* Ap = A + (size_t)(m0 + a_m) * K + a_k4;
    const float* Bp = B + (size_t)b_k * N + n0 + b_n4;

    float acc[4][4] = {};

    for (int k0 = 0; k0 < K; k0 += 16) {
        float4 av = *(const float4*)(Ap + k0);
        As[a_k4 + 0][a_m] = av.x;
        As[a_k4 + 1][a_m] = av.y;
        As[a_k4 + 2][a_m] = av.z;
        As[a_k4 + 3][a_m] = av.w;
        float4 bv = *(const float4*)(Bp + (size_t)k0 * N);
        Bs[b_k][b_n4 + 0] = bv.x;
        Bs[b_k][b_n4 + 1] = bv.y;
        Bs[b_k][b_n4 + 2] = bv.z;
        Bs[b_k][b_n4 + 3] = bv.w;
        __syncthreads();
#pragma unroll
        for (int k = 0; k < 16; k++) {
            float a[4], b[4];
#pragma unroll
            for (int i = 0; i < 4; i++) a[i] = As[k][ty + 16 * i];
#pragma unroll
            for (int j = 0; j < 4; j++) b[j] = Bs[k][tx + 16 * j];
#pragma unroll
            for (int i = 0; i < 4; i++)
#pragma unroll
                for (int j = 0; j < 4; j++)
                    acc[i][j] = fmaf(a[i], b[j], acc[i][j]);
        }
        __syncthreads();
    }

#pragma unroll
    for (int j = 0; j < 4; j++) {
        const float bj = bias[n0 + tx + 16 * j];
#pragma unroll
        for (int i = 0; i < 4; i++) {
            float c = acc[i][j] + bj;
            if (GELU) c = 0.5f * c * (1.0f + erff(c * 0.70710678118654752f));
            C[(size_t)(m0 + ty + 16 * i) * N + n0 + tx + 16 * j] = c;
        }
    }
}

// ---------------- fused attention (flash-style, fp32) ----------------
// One CTA per (b, h, 64 Q rows). Online softmax over 8 chunks of 64 keys.
#define SMPAD 65
__global__ __launch_bounds__(256) void attention_kernel(
    const float* __restrict__ q, const float* __restrict__ k,
    const float* __restrict__ v, const float* __restrict__ mask,
    float* __restrict__ ctx)
{
    extern __shared__ float sm[];
    float* Qs = sm;
    float* Ks = Qs + 64 * SMPAD;
    float* Vs = Ks + 64 * SMPAD;
    float* Ps = Vs + 64 * SMPAD;
    float* rm = Ps + 64 * SMPAD;
    float* rl = rm + 64;
    float* rs = rl + 64;
    float* am = rs + 64;

    const int tx = threadIdx.x, ty = threadIdx.y;
    const int tid = ty * 16 + tx;
    const int bh = blockIdx.y;
    const int b = bh / NHz, h = bh % NHz;
    const int i0 = blockIdx.x * 64;
    const float scale = 0.125f;  // 1/sqrt(64)

    // load Q tile [64 x 64]
#pragma unroll
    for (int it = 0; it < 4; it++) {
        int idx = tid + it * 256;
        int row = idx >> 4;
        int d4 = (idx & 15) * 4;
        float4 t = *(const float4*)(q + (size_t)(b * Tz + i0 + row) * Hz + h * HDz + d4);
        Qs[row * SMPAD + d4 + 0] = t.x;
        Qs[row * SMPAD + d4 + 1] = t.y;
        Qs[row * SMPAD + d4 + 2] = t.z;
        Qs[row * SMPAD + d4 + 3] = t.w;
    }
    if (tid < 64) { rm[tid] = -1e30f; rl[tid] = 0.0f; }

    float acc[4][4] = {};

    for (int jc = 0; jc < Tz / 64; jc++) {
        const int j0 = jc * 64;
        // load K chunk
#pragma unroll
        for (int it = 0; it < 4; it++) {
            int idx = tid + it * 256;
            int row = idx >> 4;
            int d4 = (idx & 15) * 4;
            float4 t = *(const float4*)(k + (size_t)(b * Tz + j0 + row) * Hz + h * HDz + d4);
            Ks[row * SMPAD + d4 + 0] = t.x;
            Ks[row * SMPAD + d4 + 1] = t.y;
            Ks[row * SMPAD + d4 + 2] = t.z;
            Ks[row * SMPAD + d4 + 3] = t.w;
        }
        if (tid < 64) am[tid] = (1.0f - mask[b * Tz + j0 + tid]) * -10000.0f;
        __syncthreads();

        // S = Q @ K^T (64x64)
        float s[4][4] = {};
#pragma unroll 4
        for (int d = 0; d < 64; d++) {
            float qv[4], kv[4];
#pragma unroll
            for (int i = 0; i < 4; i++) qv[i] = Qs[(ty + 16 * i) * SMPAD + d];
#pragma unroll
            for (int j = 0; j < 4; j++) kv[j] = Ks[(tx + 16 * j) * SMPAD + d];
#pragma unroll
            for (int i = 0; i < 4; i++)
#pragma unroll
                for (int j = 0; j < 4; j++)
                    s[i][j] = fmaf(qv[i], kv[j], s[i][j]);
        }
#pragma unroll
        for (int i = 0; i < 4; i++)
#pragma unroll
            for (int j = 0; j < 4; j++)
                Ps[(ty + 16 * i) * SMPAD + tx + 16 * j] = s[i][j] * scale + am[tx + 16 * j];
        __syncthreads();

        // load V chunk (all threads) + per-row online softmax stats (64 threads)
#pragma unroll
        for (int it = 0; it < 4; it++) {
            int idx = tid + it * 256;
            int row = idx >> 4;
            int d4 = (idx & 15) * 4;
            float4 t = *(const float4*)(v + (size_t)(b * Tz + j0 + row) * Hz + h * HDz + d4);
            Vs[row * SMPAD + d4 + 0] = t.x;
            Vs[row * SMPAD + d4 + 1] = t.y;
            Vs[row * SMPAD + d4 + 2] = t.z;
            Vs[row * SMPAD + d4 + 3] = t.w;
        }
        if (tid < 64) {
            const int row = tid;
            float mo = rm[row];
            float cm = -1e30f;
#pragma unroll 8
            for (int j = 0; j < 64; j++) cm = fmaxf(cm, Ps[row * SMPAD + j]);
            float nm = fmaxf(mo, cm);
            float sc = expf(mo - nm);
            float sum = 0.0f;
#pragma unroll 8
            for (int j = 0; j < 64; j++) {
                float p = expf(Ps[row * SMPAD + j] - nm);
                Ps[row * SMPAD + j] = p;
                sum += p;
            }
            rl[row] = rl[row] * sc + sum;
            rm[row] = nm;
            rs[row] = sc;
        }
        __syncthreads();

        // rescale accumulator, then O += P @ V
#pragma unroll
        for (int i = 0; i < 4; i++) {
            const float sc = rs[ty + 16 * i];
#pragma unroll
            for (int j = 0; j < 4; j++) acc[i][j] *= sc;
        }
#pragma unroll 4
        for (int jj = 0; jj < 64; jj++) {
            float pv[4], vv[4];
#pragma unroll
            for (int i = 0; i < 4; i++) pv[i] = Ps[(ty + 16 * i) * SMPAD + jj];
#pragma unroll
            for (int j = 0; j < 4; j++) vv[j] = Vs[jj * SMPAD + tx + 16 * j];
#pragma unroll
            for (int i = 0; i < 4; i++)
#pragma unroll
                for (int j = 0; j < 4; j++)
                    acc[i][j] = fmaf(pv[i], vv[j], acc[i][j]);
        }
        __syncthreads();
    }

#pragma unroll
    for (int i = 0; i < 4; i++) {
        const float inv = 1.0f / rl[ty + 16 * i];
#pragma unroll
        for (int j = 0; j < 4; j++) {
            ctx[(size_t)(b * Tz + i0 + ty + 16 * i) * Hz + h * HDz + tx + 16 * j] = acc[i][j] * inv;
        }
    }
}

// ---------------- residual + LayerNorm ----------------
__device__ __forceinline__ float block_reduce_sum(float val, float* red) {
    const int lane = threadIdx.x & 31, w = threadIdx.x >> 5;
#pragma unroll
    for (int o = 16; o > 0; o >>= 1) val += __shfl_down_sync(0xffffffffu, val, o);
    if (lane == 0) red[w] = val;
    __syncthreads();
    if (w == 0) {
        float t = (lane < 8) ? red[lane] : 0.0f;
#pragma unroll
        for (int o = 4; o > 0; o >>= 1) t += __shfl_down_sync(0xffffffffu, t, o);
        if (lane == 0) red[0] = t;
    }
    __syncthreads();
    float r = red[0];
    __syncthreads();
    return r;
}

__global__ __launch_bounds__(256) void ln_kernel(
    const float* __restrict__ a, const float* __restrict__ res,
    const float* __restrict__ g, const float* __restrict__ bb,
    float* __restrict__ out)
{
    __shared__ float buf[Hz];
    __shared__ float red[32];
    const int row = blockIdx.x;
    const float* ap = a + (size_t)row * Hz;
    const float* rp = res + (size_t)row * Hz;

    float ls = 0.0f;
    for (int i = threadIdx.x; i < Hz; i += 256) {
        float vv = ap[i] + rp[i];
        buf[i] = vv;
        ls += vv;
    }
    const float mean = block_reduce_sum(ls, red) * (1.0f / Hz);

    float lq = 0.0f;
    for (int i = threadIdx.x; i < Hz; i += 256) {
        float d = buf[i] - mean;
        lq += d * d;
    }
    const float var = block_reduce_sum(lq, red) * (1.0f / Hz);
    const float rstd = rsqrtf(var + 1e-12f);

    for (int i = threadIdx.x; i < Hz; i += 256) {
        out[(size_t)row * Hz + i] = (buf[i] - mean) * rstd * g[i] + bb[i];
    }
}

// ---------------- launch ----------------
extern "C" void kernel_launch(void* const* d_in, const int* in_sizes, int n_in,
                              void* d_out, int out_size)
{
    const float* hidden = (const float*)d_in[0];
    const float* mask   = (const float*)d_in[1];
    const float* Wq  = (const float*)d_in[2];   const float* bq  = (const float*)d_in[3];
    const float* Wk  = (const float*)d_in[4];   const float* bk  = (const float*)d_in[5];
    const float* Wv  = (const float*)d_in[6];   const float* bv  = (const float*)d_in[7];
    const float* Wao = (const float*)d_in[8];   const float* bao = (const float*)d_in[9];
    const float* g1  = (const float*)d_in[10];  const float* b1  = (const float*)d_in[11];
    const float* Wi  = (const float*)d_in[12];  const float* bi  = (const float*)d_in[13];
    const float* Wo  = (const float*)d_in[14];  const float* bo  = (const float*)d_in[15];
    const float* g2  = (const float*)d_in[16];  const float* b2  = (const float*)d_in[17];
    float* out = (float*)d_out;

    float *q, *k, *v, *ctx, *proj, *attn, *xb, *ff;
    cudaGetSymbolAddress((void**)&q,    g_q);
    cudaGetSymbolAddress((void**)&k,    g_k);
    cudaGetSymbolAddress((void**)&v,    g_v);
    cudaGetSymbolAddress((void**)&ctx,  g_ctx);
    cudaGetSymbolAddress((void**)&proj, g_proj);
    cudaGetSymbolAddress((void**)&attn, g_attn);
    cudaGetSymbolAddress((void**)&xb,   g_x);
    cudaGetSymbolAddress((void**)&ff,   g_ff);

    const size_t att_smem = (size_t)(4 * 64 * SMPAD + 4 * 64) * sizeof(float);
    cudaFuncSetAttribute(attention_kernel,
                         cudaFuncAttributeMaxDynamicSharedMemorySize, (int)att_smem);

    dim3 blk(16, 16);
    dim3 gH(Hz / 64, Mz / 64);     // (12, 64)
    dim3 gFF(FFz / 64, Mz / 64);   // (48, 64)
    dim3 gAtt(Tz / 64, Bz * NHz);  // (8, 96)

    for (int l = 0; l < Lz; l++) {
        const float* x = (l == 0) ? hidden : xb;
        const size_t oHH = (size_t)l * Hz * Hz;
        const size_t oHF = (size_t)l * Hz * FFz;

        gemm_bias_kernel<false><<<gH, blk>>>(x,   Wq + oHH, bq + (size_t)l * Hz, q, Mz, Hz, Hz);
        gemm_bias_kernel<false><<<gH, blk>>>(x,   Wk + oHH, bk + (size_t)l * Hz, k, Mz, Hz, Hz);
        gemm_bias_kernel<false><<<gH, blk>>>(x,   Wv + oHH, bv + (size_t)l * Hz, v, Mz, Hz, Hz);

        attention_kernel<<<gAtt, blk, att_smem>>>(q, k, v, mask, ctx);

        gemm_bias_kernel<false><<<gH, blk>>>(ctx, Wao + oHH, bao + (size_t)l * Hz, proj, Mz, Hz, Hz);
        ln_kernel<<<Mz, 256>>>(proj, x, g1 + (size_t)l * Hz, b1 + (size_t)l * Hz, attn);

        gemm_bias_kernel<true ><<<gFF, blk>>>(attn, Wi + oHF, bi + (size_t)l * FFz, ff,   Mz, FFz, Hz);
        gemm_bias_kernel<false><<<gH,  blk>>>(ff,   Wo + oHF, bo + (size_t)l * Hz,  proj, Mz, Hz, FFz);
        ln_kernel<<<Mz, 256>>>(proj, attn, g2 + (size_t)l * Hz, b2 + (size_t)l * Hz,
                               (l == Lz - 1) ? out : xb);
    }
}

// round 2
// speedup vs baseline: 2.0021x; 2.0021x over previous
#include <cuda_runtime.h>
#include <cuda_bf16.h>
#include <math.h>
#include <stdint.h>

#define Bz  8
#define Tz  512
#define Hz  768
#define NHz 12
#define HDz 64
#define FFz 3072
#define Lz  12
#define Mz  (Bz*Tz)   // 4096

// ---------------- scratch (no allocation allowed) ----------------
__device__ float g_qkv[3 * Mz * Hz];
__device__ float g_ctx[Mz * Hz];
__device__ float g_proj[Mz * Hz];
__device__ float g_attn[Mz * Hz];
__device__ float g_x[Mz * Hz];
__device__ float g_ff[Mz * FFz];

// ================= bf16x3 tensor-core GEMM =================
// C[M,N] = A[M,K] @ W[K,N] + bias (+optional exact GELU)
// CTA tile 128x128, BK=16, 8 warps (2x4), warp tile 64x32, m16n8k16 bf16 mma,
// 3-term split: hi*hi + hi*lo + lo*hi (fp32 accumulate).
#define BM 128
#define BN 128
#define BKg 16
#define ALD 24    // As leading dim (bf16 elems): 12 words/row -> conflict-free ldmatrix
#define BLD 136   // Bs leading dim: 68 words/row -> conflict-free per ldmatrix phase

struct GemmPtrs {
    const float* W[3];
    const float* bias[3];
    float*       C[3];
};

__device__ __forceinline__ void ldsm4(uint32_t* r, const void* p) {
    uint32_t a = (uint32_t)__cvta_generic_to_shared(p);
    asm volatile("ldmatrix.sync.aligned.m8n8.x4.shared.b16 {%0,%1,%2,%3}, [%4];"
                 : "=r"(r[0]), "=r"(r[1]), "=r"(r[2]), "=r"(r[3]) : "r"(a));
}
__device__ __forceinline__ void ldsm4t(uint32_t* r, const void* p) {
    uint32_t a = (uint32_t)__cvta_generic_to_shared(p);
    asm volatile("ldmatrix.sync.aligned.m8n8.x4.trans.shared.b16 {%0,%1,%2,%3}, [%4];"
                 : "=r"(r[0]), "=r"(r[1]), "=r"(r[2]), "=r"(r[3]) : "r"(a));
}
__device__ __forceinline__ void mma16816(float* c, const uint32_t* a, const uint32_t* b) {
    asm volatile(
        "mma.sync.aligned.m16n8k16.row.col.f32.bf16.bf16.f32 "
        "{%0,%1,%2,%3}, {%4,%5,%6,%7}, {%8,%9}, {%0,%1,%2,%3};"
        : "+f"(c[0]), "+f"(c[1]), "+f"(c[2]), "+f"(c[3])
        : "r"(a[0]), "r"(a[1]), "r"(a[2]), "r"(a[3]), "r"(b[0]), "r"(b[1]));
}

// split two floats into packed bf16x2 hi and lo
__device__ __forceinline__ void split2(float x, float y, uint32_t& hi, uint32_t& lo) {
    __nv_bfloat16 xh = __float2bfloat16(x);
    __nv_bfloat16 yh = __float2bfloat16(y);
    __nv_bfloat16 xl = __float2bfloat16(x - __bfloat162float(xh));
    __nv_bfloat16 yl = __float2bfloat16(y - __bfloat162float(yh));
    hi = (uint32_t)__bfloat16_as_ushort(xh) | ((uint32_t)__bfloat16_as_ushort(yh) << 16);
    lo = (uint32_t)__bfloat16_as_ushort(xl) | ((uint32_t)__bfloat16_as_ushort(yl) << 16);
}

template<bool GELU>
__global__ __launch_bounds__(256, 1) void gemm_bf16x3(
    const float* __restrict__ A, GemmPtrs P, int K, int N)
{
    __shared__ __align__(16) __nv_bfloat16 As[2][2][BM][ALD];  // [buf][hi/lo][m][k]
    __shared__ __align__(16) __nv_bfloat16 Bs[2][2][BKg][BLD]; // [buf][hi/lo][k][n]

    const int z = blockIdx.z;
    const float* __restrict__ Wp   = P.W[z];
    const float* __restrict__ bias = P.bias[z];
    float* __restrict__ C          = P.C[z];

    const int n0 = blockIdx.x * BN;
    const int m0 = blockIdx.y * BM;
    const int tid  = threadIdx.x;
    const int lane = tid & 31;
    const int warp = tid >> 5;
    const int warpM = warp >> 2;   // 0..1
    const int warpN = warp & 3;    // 0..3

    // loader coordinates
    const int arow0 = tid >> 2;          // 0..63 (+64 on pass 1)
    const int akc   = (tid & 3) * 4;     // 0,4,8,12
    const int brow0 = tid >> 5;          // 0..7  (+8 on pass 1)
    const int bnc   = (tid & 31) * 4;    // 0..124

    float ra[8], rb[8];

    auto loadRegs = [&](int t) {
        const int k0 = t * BKg;
#pragma unroll
        for (int p = 0; p < 2; p++) {
            float4 va = *(const float4*)(A + (size_t)(m0 + arow0 + p * 64) * K + k0 + akc);
            ra[p * 4 + 0] = va.x; ra[p * 4 + 1] = va.y; ra[p * 4 + 2] = va.z; ra[p * 4 + 3] = va.w;
            float4 vb = *(const float4*)(Wp + (size_t)(k0 + brow0 + p * 8) * N + n0 + bnc);
            rb[p * 4 + 0] = vb.x; rb[p * 4 + 1] = vb.y; rb[p * 4 + 2] = vb.z; rb[p * 4 + 3] = vb.w;
        }
    };
    auto storeSmem = [&](int buf) {
#pragma unroll
        for (int p = 0; p < 2; p++) {
            uint32_t h0, l0, h1, l1;
            split2(ra[p * 4 + 0], ra[p * 4 + 1], h0, l0);
            split2(ra[p * 4 + 2], ra[p * 4 + 3], h1, l1);
            *(uint2*)&As[buf][0][arow0 + p * 64][akc] = make_uint2(h0, h1);
            *(uint2*)&As[buf][1][arow0 + p * 64][akc] = make_uint2(l0, l1);
            split2(rb[p * 4 + 0], rb[p * 4 + 1], h0, l0);
            split2(rb[p * 4 + 2], rb[p * 4 + 3], h1, l1);
            *(uint2*)&Bs[buf][0][brow0 + p * 8][bnc] = make_uint2(h0, h1);
            *(uint2*)&Bs[buf][1][brow0 + p * 8][bnc] = make_uint2(l0, l1);
        }
    };

    float acc[4][4][4] = {};

    const int nT = K / BKg;
    loadRegs(0);
    storeSmem(0);
    __syncthreads();

    for (int t = 0; t < nT; t++) {
        if (t + 1 < nT) loadRegs(t + 1);
        const int buf = t & 1;

        // A fragments (4 m-tiles, hi & lo)
        uint32_t ah[4][4], al[4][4];
        const int arow = warpM * 64 + (lane & 15);
        const int acol = (lane >> 4) * 8;
#pragma unroll
        for (int mi = 0; mi < 4; mi++) {
            ldsm4(ah[mi], &As[buf][0][arow + mi * 16][acol]);
            ldsm4(al[mi], &As[buf][1][arow + mi * 16][acol]);
        }
        // B fragments (4 n-tiles, hi & lo) -- x4.trans gives two n-tiles per load
        uint32_t bh[4][2], bl[4][2];
        const int brow = (lane & 15);
#pragma unroll
        for (int pr = 0; pr < 2; pr++) {
            const int bcol = warpN * 32 + pr * 16 + (lane >> 4) * 8;
            uint32_t tmp[4];
            ldsm4t(tmp, &Bs[buf][0][brow][bcol]);
            bh[pr * 2][0] = tmp[0]; bh[pr * 2][1] = tmp[1];
            bh[pr * 2 + 1][0] = tmp[2]; bh[pr * 2 + 1][1] = tmp[3];
            ldsm4t(tmp, &Bs[buf][1][brow][bcol]);
            bl[pr * 2][0] = tmp[0]; bl[pr * 2][1] = tmp[1];
            bl[pr * 2 + 1][0] = tmp[2]; bl[pr * 2 + 1][1] = tmp[3];
        }
#pragma unroll
        for (int mi = 0; mi < 4; mi++)
#pragma unroll
            for (int ni = 0; ni < 4; ni++) {
                mma16816(acc[mi][ni], ah[mi], bh[ni]);
                mma16816(acc[mi][ni], ah[mi], bl[ni]);
                mma16816(acc[mi][ni], al[mi], bh[ni]);
            }

        if (t + 1 < nT) storeSmem((t + 1) & 1);
        __syncthreads();
    }

    // epilogue
    const int g  = lane >> 2;
    const int tg = lane & 3;
#pragma unroll
    for (int mi = 0; mi < 4; mi++) {
#pragma unroll
        for (int ni = 0; ni < 4; ni++) {
            const int row = m0 + warpM * 64 + mi * 16 + g;
            const int col = n0 + warpN * 32 + ni * 8 + tg * 2;
            const float b0 = bias[col], b1 = bias[col + 1];
            float v0 = acc[mi][ni][0] + b0;
            float v1 = acc[mi][ni][1] + b1;
            float v2 = acc[mi][ni][2] + b0;
            float v3 = acc[mi][ni][3] + b1;
            if (GELU) {
                v0 = 0.5f * v0 * (1.0f + erff(v0 * 0.70710678118654752f));
                v1 = 0.5f * v1 * (1.0f + erff(v1 * 0.70710678118654752f));
                v2 = 0.5f * v2 * (1.0f + erff(v2 * 0.70710678118654752f));
                v3 = 0.5f * v3 * (1.0f + erff(v3 * 0.70710678118654752f));
            }
            *(float2*)(C + (size_t)row * N + col)       = make_float2(v0, v1);
            *(float2*)(C + (size_t)(row + 8) * N + col) = make_float2(v2, v3);
        }
    }
}

// ---------------- fused attention (flash-style, fp32) ----------------
#define SMPAD 65
__global__ __launch_bounds__(256) void attention_kernel(
    const float* __restrict__ q, const float* __restrict__ k,
    const float* __restrict__ v, const float* __restrict__ mask,
    float* __restrict__ ctx)
{
    extern __shared__ float sm[];
    float* Qs = sm;
    float* Ks = Qs + 64 * SMPAD;
    float* Vs = Ks + 64 * SMPAD;
    float* Ps = Vs + 64 * SMPAD;
    float* rm = Ps + 64 * SMPAD;
    float* rl = rm + 64;
    float* rs = rl + 64;
    float* am = rs + 64;

    const int tx = threadIdx.x, ty = threadIdx.y;
    const int tid = ty * 16 + tx;
    const int bh = blockIdx.y;
    const int b = bh / NHz, h = bh % NHz;
    const int i0 = blockIdx.x * 64;
    const float scale = 0.125f;

#pragma unroll
    for (int it = 0; it < 4; it++) {
        int idx = tid + it * 256;
        int row = idx >> 4;
        int d4 = (idx & 15) * 4;
        float4 t = *(const float4*)(q + (size_t)(b * Tz + i0 + row) * Hz + h * HDz + d4);
        Qs[row * SMPAD + d4 + 0] = t.x;
        Qs[row * SMPAD + d4 + 1] = t.y;
        Qs[row * SMPAD + d4 + 2] = t.z;
        Qs[row * SMPAD + d4 + 3] = t.w;
    }
    if (tid < 64) { rm[tid] = -1e30f; rl[tid] = 0.0f; }

    float acc[4][4] = {};

    for (int jc = 0; jc < Tz / 64; jc++) {
        const int j0 = jc * 64;
#pragma unroll
        for (int it = 0; it < 4; it++) {
            int idx = tid + it * 256;
            int row = idx >> 4;
            int d4 = (idx & 15) * 4;
            float4 t = *(const float4*)(k + (size_t)(b * Tz + j0 + row) * Hz + h * HDz + d4);
            Ks[row * SMPAD + d4 + 0] = t.x;
            Ks[row * SMPAD + d4 + 1] = t.y;
            Ks[row * SMPAD + d4 + 2] = t.z;
            Ks[row * SMPAD + d4 + 3] = t.w;
        }
        if (tid < 64) am[tid] = (1.0f - mask[b * Tz + j0 + tid]) * -10000.0f;
        __syncthreads();

        float s[4][4] = {};
#pragma unroll 4
        for (int d = 0; d < 64; d++) {
            float qv[4], kv[4];
#pragma unroll
            for (int i = 0; i < 4; i++) qv[i] = Qs[(ty + 16 * i) * SMPAD + d];
#pragma unroll
            for (int j = 0; j < 4; j++) kv[j] = Ks[(tx + 16 * j) * SMPAD + d];
#pragma unroll
            for (int i = 0; i < 4; i++)
#pragma unroll
                for (int j = 0; j < 4; j++)
                    s[i][j] = fmaf(qv[i], kv[j], s[i][j]);
        }
#pragma unroll
        for (int i = 0; i < 4; i++)
#pragma unroll
            for (int j = 0; j < 4; j++)
                Ps[(ty + 16 * i) * SMPAD + tx + 16 * j] = s[i][j] * scale + am[tx + 16 * j];
        __syncthreads();

#pragma unroll
        for (int it = 0; it < 4; it++) {
            int idx = tid + it * 256;
            int row = idx >> 4;
            int d4 = (idx & 15) * 4;
            float4 t = *(const float4*)(v + (size_t)(b * Tz + j0 + row) * Hz + h * HDz + d4);
            Vs[row * SMPAD + d4 + 0] = t.x;
            Vs[row * SMPAD + d4 + 1] = t.y;
            Vs[row * SMPAD + d4 + 2] = t.z;
            Vs[row * SMPAD + d4 + 3] = t.w;
        }
        if (tid < 64) {
            const int row = tid;
            float mo = rm[row];
            float cm = -1e30f;
#pragma unroll 8
            for (int j = 0; j < 64; j++) cm = fmaxf(cm, Ps[row * SMPAD + j]);
            float nm = fmaxf(mo, cm);
            float sc = expf(mo - nm);
            float sum = 0.0f;
#pragma unroll 8
            for (int j = 0; j < 64; j++) {
                float p = expf(Ps[row * SMPAD + j] - nm);
                Ps[row * SMPAD + j] = p;
                sum += p;
            }
            rl[row] = rl[row] * sc + sum;
            rm[row] = nm;
            rs[row] = sc;
        }
        __syncthreads();

#pragma unroll
        for (int i = 0; i < 4; i++) {
            const float sc = rs[ty + 16 * i];
#pragma unroll
            for (int j = 0; j < 4; j++) acc[i][j] *= sc;
        }
#pragma unroll 4
        for (int jj = 0; jj < 64; jj++) {
            float pv[4], vv[4];
#pragma unroll
            for (int i = 0; i < 4; i++) pv[i] = Ps[(ty + 16 * i) * SMPAD + jj];
#pragma unroll
            for (int j = 0; j < 4; j++) vv[j] = Vs[jj * SMPAD + tx + 16 * j];
#pragma unroll
            for (int i = 0; i < 4; i++)
#pragma unroll
                for (int j = 0; j < 4; j++)
                    acc[i][j] = fmaf(pv[i], vv[j], acc[i][j]);
        }
        __syncthreads();
    }

#pragma unroll
    for (int i = 0; i < 4; i++) {
        const float inv = 1.0f / rl[ty + 16 * i];
#pragma unroll
        for (int j = 0; j < 4; j++) {
            ctx[(size_t)(b * Tz + i0 + ty + 16 * i) * Hz + h * HDz + tx + 16 * j] = acc[i][j] * inv;
        }
    }
}

// ---------------- residual + LayerNorm ----------------
__device__ __forceinline__ float block_reduce_sum(float val, float* red) {
    const int lane = threadIdx.x & 31, w = threadIdx.x >> 5;
#pragma unroll
    for (int o = 16; o > 0; o >>= 1) val += __shfl_down_sync(0xffffffffu, val, o);
    if (lane == 0) red[w] = val;
    __syncthreads();
    if (w == 0) {
        float t = (lane < 8) ? red[lane] : 0.0f;
#pragma unroll
        for (int o = 4; o > 0; o >>= 1) t += __shfl_down_sync(0xffffffffu, t, o);
        if (lane == 0) red[0] = t;
    }
    __syncthreads();
    float r = red[0];
    __syncthreads();
    return r;
}

__global__ __launch_bounds__(256) void ln_kernel(
    const float* __restrict__ a, const float* __restrict__ res,
    const float* __restrict__ g, const float* __restrict__ bb,
    float* __restrict__ out)
{
    __shared__ float buf[Hz];
    __shared__ float red[32];
    const int row = blockIdx.x;
    const float* ap = a + (size_t)row * Hz;
    const float* rp = res + (size_t)row * Hz;

    float ls = 0.0f;
    for (int i = threadIdx.x; i < Hz; i += 256) {
        float vv = ap[i] + rp[i];
        buf[i] = vv;
        ls += vv;
    }
    const float mean = block_reduce_sum(ls, red) * (1.0f / Hz);

    float lq = 0.0f;
    for (int i = threadIdx.x; i < Hz; i += 256) {
        float d = buf[i] - mean;
        lq += d * d;
    }
    const float var = block_reduce_sum(lq, red) * (1.0f / Hz);
    const float rstd = rsqrtf(var + 1e-12f);

    for (int i = threadIdx.x; i < Hz; i += 256) {
        out[(size_t)row * Hz + i] = (buf[i] - mean) * rstd * g[i] + bb[i];
    }
}

// ---------------- launch ----------------
extern "C" void kernel_launch(void* const* d_in, const int* in_sizes, int n_in,
                              void* d_out, int out_size)
{
    const float* hidden = (const float*)d_in[0];
    const float* mask   = (const float*)d_in[1];
    const float* Wq  = (const float*)d_in[2];   const float* bq  = (const float*)d_in[3];
    const float* Wk  = (const float*)d_in[4];   const float* bk  = (const float*)d_in[5];
    const float* Wv  = (const float*)d_in[6];   const float* bv  = (const float*)d_in[7];
    const float* Wao = (const float*)d_in[8];   const float* bao = (const float*)d_in[9];
    const float* g1  = (const float*)d_in[10];  const float* b1  = (const float*)d_in[11];
    const float* Wi  = (const float*)d_in[12];  const float* bi  = (const float*)d_in[13];
    const float* Wo  = (const float*)d_in[14];  const float* bo  = (const float*)d_in[15];
    const float* g2  = (const float*)d_in[16];  const float* b2  = (const float*)d_in[17];
    float* out = (float*)d_out;

    float *qkv, *ctx, *proj, *attn, *xb, *ff;
    cudaGetSymbolAddress((void**)&qkv,  g_qkv);
    cudaGetSymbolAddress((void**)&ctx,  g_ctx);
    cudaGetSymbolAddress((void**)&proj, g_proj);
    cudaGetSymbolAddress((void**)&attn, g_attn);
    cudaGetSymbolAddress((void**)&xb,   g_x);
    cudaGetSymbolAddress((void**)&ff,   g_ff);
    float* q = qkv;
    float* k = qkv + (size_t)Mz * Hz;
    float* v = qkv + 2 * (size_t)Mz * Hz;

    const size_t att_smem = (size_t)(4 * 64 * SMPAD + 4 * 64) * sizeof(float);
    cudaFuncSetAttribute(attention_kernel,
                         cudaFuncAttributeMaxDynamicSharedMemorySize, (int)att_smem);

    dim3 gAtt(Tz / 64, Bz * NHz);
    dim3 blkA(16, 16);

    for (int l = 0; l < Lz; l++) {
        const float* x = (l == 0) ? hidden : xb;
        const size_t oHH = (size_t)l * Hz * Hz;
        const size_t oHF = (size_t)l * Hz * FFz;
        const size_t oH  = (size_t)l * Hz;
        const size_t oF  = (size_t)l * FFz;

        // fused QKV: gridDim.z = 3
        {
            GemmPtrs P;
            P.W[0] = Wq + oHH; P.W[1] = Wk + oHH; P.W[2] = Wv + oHH;
            P.bias[0] = bq + oH; P.bias[1] = bk + oH; P.bias[2] = bv + oH;
            P.C[0] = q; P.C[1] = k; P.C[2] = v;
            gemm_bf16x3<false><<<dim3(Hz / BN, Mz / BM, 3), 256>>>(x, P, Hz, Hz);
        }

        attention_kernel<<<gAtt, blkA, att_smem>>>(q, k, v, mask, ctx);

        {
            GemmPtrs P;
            P.W[0] = P.W[1] = P.W[2] = Wao + oHH;
            P.bias[0] = P.bias[1] = P.bias[2] = bao + oH;
            P.C[0] = P.C[1] = P.C[2] = proj;
            gemm_bf16x3<false><<<dim3(Hz / BN, Mz / BM, 1), 256>>>(ctx, P, Hz, Hz);
        }
        ln_kernel<<<Mz, 256>>>(proj, x, g1 + oH, b1 + oH, attn);

        {
            GemmPtrs P;
            P.W[0] = P.W[1] = P.W[2] = Wi + oHF;
            P.bias[0] = P.bias[1] = P.bias[2] = bi + oF;
            P.C[0] = P.C[1] = P.C[2] = ff;
            gemm_bf16x3<true><<<dim3(FFz / BN, Mz / BM, 1), 256>>>(attn, P, Hz, FFz);
        }
        {
            GemmPtrs P;
            P.W[0] = P.W[1] = P.W[2] = Wo + oHF;
            P.bias[0] = P.bias[1] = P.bias[2] = bo + oH;
            P.C[0] = P.C[1] = P.C[2] = proj;
            gemm_bf16x3<false><<<dim3(Hz / BN, Mz / BM, 1), 256>>>(ff, P, FFz, Hz);
        }
        ln_kernel<<<Mz, 256>>>(proj, attn, g2 + oH, b2 + oH,
                               (l == Lz - 1) ? out : xb);
    }
}

// round 3
// speedup vs baseline: 2.1648x; 1.0813x over previous
#include <cuda_runtime.h>
#include <cuda_bf16.h>
#include <math.h>
#include <stdint.h>

#define Bz  8
#define Tz  512
#define Hz  768
#define NHz 12
#define HDz 64
#define FFz 3072
#define Lz  12
#define Mz  (Bz*Tz)   // 4096

// ---------------- fp32 scratch ----------------
__device__ float g_q[Mz*Hz];
__device__ float g_k[Mz*Hz];
__device__ float g_v[Mz*Hz];
__device__ float g_proj[Mz*Hz];
__device__ float g_attn[Mz*Hz];
__device__ float g_x[Mz*Hz];

// ---------------- split (hi/lo bf16) activation scratch ----------------
__device__ __nv_bfloat16 g_x_h[Mz*Hz],    g_x_l[Mz*Hz];
__device__ __nv_bfloat16 g_attn_h[Mz*Hz], g_attn_l[Mz*Hz];
__device__ __nv_bfloat16 g_ctx_h[Mz*Hz],  g_ctx_l[Mz*Hz];
__device__ __nv_bfloat16 g_ff_h[Mz*FFz],  g_ff_l[Mz*FFz];

// ---------------- split weight storage ----------------
__device__ __nv_bfloat16 g_wq_h[Lz*Hz*Hz],  g_wq_l[Lz*Hz*Hz];
__device__ __nv_bfloat16 g_wk_h[Lz*Hz*Hz],  g_wk_l[Lz*Hz*Hz];
__device__ __nv_bfloat16 g_wv_h[Lz*Hz*Hz],  g_wv_l[Lz*Hz*Hz];
__device__ __nv_bfloat16 g_wao_h[Lz*Hz*Hz], g_wao_l[Lz*Hz*Hz];
__device__ __nv_bfloat16 g_wi_h[Lz*Hz*FFz], g_wi_l[Lz*Hz*FFz];
__device__ __nv_bfloat16 g_wo_h[Lz*Hz*FFz], g_wo_l[Lz*Hz*FFz];

// ---------------- helpers ----------------
__device__ __forceinline__ void split1(float x, __nv_bfloat16& h, __nv_bfloat16& l) {
    h = __float2bfloat16(x);
    l = __float2bfloat16(x - __bfloat162float(h));
}
__device__ __forceinline__ void split2(float x, float y, uint32_t& hi, uint32_t& lo) {
    __nv_bfloat16 xh, xl, yh, yl;
    split1(x, xh, xl); split1(y, yh, yl);
    hi = (uint32_t)__bfloat16_as_ushort(xh) | ((uint32_t)__bfloat16_as_ushort(yh) << 16);
    lo = (uint32_t)__bfloat16_as_ushort(xl) | ((uint32_t)__bfloat16_as_ushort(yl) << 16);
}

__global__ __launch_bounds__(256) void split_kernel(
    const float* __restrict__ in, __nv_bfloat16* __restrict__ h,
    __nv_bfloat16* __restrict__ l, int n4)
{
    int i = blockIdx.x * 256 + threadIdx.x;
    if (i >= n4) return;
    float4 v = ((const float4*)in)[i];
    uint32_t h01, l01, h23, l23;
    split2(v.x, v.y, h01, l01);
    split2(v.z, v.w, h23, l23);
    ((uint2*)h)[i] = make_uint2(h01, h23);
    ((uint2*)l)[i] = make_uint2(l01, l23);
}

// ================= bf16x3 tensor-core GEMM (pre-split operands) =================
#define BM 128
#define BN 128
#define BKg 16
#define ALD 24
#define BLD 136
#define STG 3

#define ASOFF(s,hl,m,k)  (((((s)*2+(hl))*BM)+(m))*ALD+(k))
#define BSOFF(s,hl,kk,n) (((((s)*2+(hl))*BKg)+(kk))*BLD+(n))

struct GemmArgs {
    const __nv_bfloat16 *Ah, *Al;
    const __nv_bfloat16 *Bh[3], *Bl[3];
    const float* bias[3];
    float* C[3];
    __nv_bfloat16 *Ch, *Cl;
};

__device__ __forceinline__ void cpasync16(void* dst, const void* src) {
    uint32_t d = (uint32_t)__cvta_generic_to_shared(dst);
    asm volatile("cp.async.cg.shared.global [%0], [%1], 16;" :: "r"(d), "l"(src));
}
__device__ __forceinline__ void ldsm4(uint32_t* r, const void* p) {
    uint32_t a = (uint32_t)__cvta_generic_to_shared(p);
    asm volatile("ldmatrix.sync.aligned.m8n8.x4.shared.b16 {%0,%1,%2,%3}, [%4];"
                 : "=r"(r[0]), "=r"(r[1]), "=r"(r[2]), "=r"(r[3]) : "r"(a));
}
__device__ __forceinline__ void ldsm4t(uint32_t* r, const void* p) {
    uint32_t a = (uint32_t)__cvta_generic_to_shared(p);
    asm volatile("ldmatrix.sync.aligned.m8n8.x4.trans.shared.b16 {%0,%1,%2,%3}, [%4];"
                 : "=r"(r[0]), "=r"(r[1]), "=r"(r[2]), "=r"(r[3]) : "r"(a));
}
__device__ __forceinline__ void mma16816(float* c, const uint32_t* a, const uint32_t* b) {
    asm volatile(
        "mma.sync.aligned.m16n8k16.row.col.f32.bf16.bf16.f32 "
        "{%0,%1,%2,%3}, {%4,%5,%6,%7}, {%8,%9}, {%0,%1,%2,%3};"
        : "+f"(c[0]), "+f"(c[1]), "+f"(c[2]), "+f"(c[3])
        : "r"(a[0]), "r"(a[1]), "r"(a[2]), "r"(a[3]), "r"(b[0]), "r"(b[1]));
}

// MODE 0: fp32 out (+bias). MODE 1: bias + exact GELU, split bf16 out.
template<int MODE>
__global__ __launch_bounds__(256, 1) void gemm_bf16x3(GemmArgs P, int K, int N)
{
    extern __shared__ __align__(16) __nv_bfloat16 dsm[];
    __nv_bfloat16* As = dsm;                        // [STG][2][BM][ALD]
    __nv_bfloat16* Bs = dsm + STG * 2 * BM * ALD;   // [STG][2][BKg][BLD]

    const int z = blockIdx.z;
    const __nv_bfloat16* __restrict__ Ah = P.Ah;
    const __nv_bfloat16* __restrict__ Al = P.Al;
    const __nv_bfloat16* __restrict__ Bh = P.Bh[z];
    const __nv_bfloat16* __restrict__ Bl = P.Bl[z];
    const float* __restrict__ bias = P.bias[z];

    const int n0 = blockIdx.x * BN;
    const int m0 = blockIdx.y * BM;
    const int tid  = threadIdx.x;
    const int lane = tid & 31;
    const int warp = tid >> 5;
    const int warpM = warp >> 2;
    const int warpN = warp & 3;

    const int a_row = tid >> 1;          // 0..127
    const int a_kc  = (tid & 1) * 8;     // 0,8
    const int b_row = tid >> 4;          // 0..15
    const int b_nc  = (tid & 15) * 8;    // 0..120

    const int nT = K / BKg;

    auto issue = [&](int t, int s) {
        const int k0 = t * BKg;
        cpasync16(As + ASOFF(s, 0, a_row, a_kc), Ah + (size_t)(m0 + a_row) * K + k0 + a_kc);
        cpasync16(As + ASOFF(s, 1, a_row, a_kc), Al + (size_t)(m0 + a_row) * K + k0 + a_kc);
        cpasync16(Bs + BSOFF(s, 0, b_row, b_nc), Bh + (size_t)(k0 + b_row) * N + n0 + b_nc);
        cpasync16(Bs + BSOFF(s, 1, b_row, b_nc), Bl + (size_t)(k0 + b_row) * N + n0 + b_nc);
        asm volatile("cp.async.commit_group;");
    };

    issue(0, 0);
    issue(1, 1);

    float acc[4][4][4] = {};

    for (int t = 0; t < nT; t++) {
        asm volatile("cp.async.wait_group 1;");
        __syncthreads();
        if (t + 2 < nT) issue(t + 2, (t + 2) % STG);
        const int s = t % STG;

        uint32_t ah[4][4], al[4][4];
        const int arow = warpM * 64 + (lane & 15);
        const int acol = (lane >> 4) * 8;
#pragma unroll
        for (int mi = 0; mi < 4; mi++) {
            ldsm4(ah[mi], As + ASOFF(s, 0, arow + mi * 16, acol));
            ldsm4(al[mi], As + ASOFF(s, 1, arow + mi * 16, acol));
        }
        uint32_t bh[4][2], bl[4][2];
        const int brow = (lane & 15);
#pragma unroll
        for (int pr = 0; pr < 2; pr++) {
            const int bcol = warpN * 32 + pr * 16 + (lane >> 4) * 8;
            uint32_t tmp[4];
            ldsm4t(tmp, Bs + BSOFF(s, 0, brow, bcol));
            bh[pr * 2][0] = tmp[0]; bh[pr * 2][1] = tmp[1];
            bh[pr * 2 + 1][0] = tmp[2]; bh[pr * 2 + 1][1] = tmp[3];
            ldsm4t(tmp, Bs + BSOFF(s, 1, brow, bcol));
            bl[pr * 2][0] = tmp[0]; bl[pr * 2][1] = tmp[1];
            bl[pr * 2 + 1][0] = tmp[2]; bl[pr * 2 + 1][1] = tmp[3];
        }
#pragma unroll
        for (int mi = 0; mi < 4; mi++)
#pragma unroll
            for (int ni = 0; ni < 4; ni++) {
                mma16816(acc[mi][ni], ah[mi], bh[ni]);
                mma16816(acc[mi][ni], ah[mi], bl[ni]);
                mma16816(acc[mi][ni], al[mi], bh[ni]);
            }
    }

    const int g  = lane >> 2;
    const int tg = lane & 3;
#pragma unroll
    for (int mi = 0; mi < 4; mi++) {
#pragma unroll
        for (int ni = 0; ni < 4; ni++) {
            const int row = m0 + warpM * 64 + mi * 16 + g;
            const int col = n0 + warpN * 32 + ni * 8 + tg * 2;
            const float b0 = bias[col], b1 = bias[col + 1];
            float v0 = acc[mi][ni][0] + b0;
            float v1 = acc[mi][ni][1] + b1;
            float v2 = acc[mi][ni][2] + b0;
            float v3 = acc[mi][ni][3] + b1;
            if (MODE == 1) {
                v0 = 0.5f * v0 * (1.0f + erff(v0 * 0.70710678118654752f));
                v1 = 0.5f * v1 * (1.0f + erff(v1 * 0.70710678118654752f));
                v2 = 0.5f * v2 * (1.0f + erff(v2 * 0.70710678118654752f));
                v3 = 0.5f * v3 * (1.0f + erff(v3 * 0.70710678118654752f));
                uint32_t hw, lw;
                split2(v0, v1, hw, lw);
                *(uint32_t*)(P.Ch + (size_t)row * N + col) = hw;
                *(uint32_t*)(P.Cl + (size_t)row * N + col) = lw;
                split2(v2, v3, hw, lw);
                *(uint32_t*)(P.Ch + (size_t)(row + 8) * N + col) = hw;
                *(uint32_t*)(P.Cl + (size_t)(row + 8) * N + col) = lw;
            } else {
                float* C = P.C[z];
                *(float2*)(C + (size_t)row * N + col)       = make_float2(v0, v1);
                *(float2*)(C + (size_t)(row + 8) * N + col) = make_float2(v2, v3);
            }
        }
    }
}

// ---------------- fused attention (flash-style, fp32; split bf16 out) ----------------
#define SMPAD 65
__global__ __launch_bounds__(256) void attention_kernel(
    const float* __restrict__ q, const float* __restrict__ k,
    const float* __restrict__ v, const float* __restrict__ mask,
    __nv_bfloat16* __restrict__ ctx_h, __nv_bfloat16* __restrict__ ctx_l)
{
    extern __shared__ float sm[];
    float* Qs = sm;
    float* Ks = Qs + 64 * SMPAD;
    float* Vs = Ks + 64 * SMPAD;
    float* Ps = Vs + 64 * SMPAD;
    float* rm = Ps + 64 * SMPAD;
    float* rl = rm + 64;
    float* rs = rl + 64;
    float* am = rs + 64;

    const int tx = threadIdx.x, ty = threadIdx.y;
    const int tid = ty * 16 + tx;
    const int bh = blockIdx.y;
    const int b = bh / NHz, h = bh % NHz;
    const int i0 = blockIdx.x * 64;
    const float scale = 0.125f;

#pragma unroll
    for (int it = 0; it < 4; it++) {
        int idx = tid + it * 256;
        int row = idx >> 4;
        int d4 = (idx & 15) * 4;
        float4 t = *(const float4*)(q + (size_t)(b * Tz + i0 + row) * Hz + h * HDz + d4);
        Qs[row * SMPAD + d4 + 0] = t.x;
        Qs[row * SMPAD + d4 + 1] = t.y;
        Qs[row * SMPAD + d4 + 2] = t.z;
        Qs[row * SMPAD + d4 + 3] = t.w;
    }
    if (tid < 64) { rm[tid] = -1e30f; rl[tid] = 0.0f; }

    float acc[4][4] = {};

    for (int jc = 0; jc < Tz / 64; jc++) {
        const int j0 = jc * 64;
#pragma unroll
        for (int it = 0; it < 4; it++) {
            int idx = tid + it * 256;
            int row = idx >> 4;
            int d4 = (idx & 15) * 4;
            float4 t = *(const float4*)(k + (size_t)(b * Tz + j0 + row) * Hz + h * HDz + d4);
            Ks[row * SMPAD + d4 + 0] = t.x;
            Ks[row * SMPAD + d4 + 1] = t.y;
            Ks[row * SMPAD + d4 + 2] = t.z;
            Ks[row * SMPAD + d4 + 3] = t.w;
        }
        if (tid < 64) am[tid] = (1.0f - mask[b * Tz + j0 + tid]) * -10000.0f;
        __syncthreads();

        float s[4][4] = {};
#pragma unroll 4
        for (int d = 0; d < 64; d++) {
            float qv[4], kv[4];
#pragma unroll
            for (int i = 0; i < 4; i++) qv[i] = Qs[(ty + 16 * i) * SMPAD + d];
#pragma unroll
            for (int j = 0; j < 4; j++) kv[j] = Ks[(tx + 16 * j) * SMPAD + d];
#pragma unroll
            for (int i = 0; i < 4; i++)
#pragma unroll
                for (int j = 0; j < 4; j++)
                    s[i][j] = fmaf(qv[i], kv[j], s[i][j]);
        }
#pragma unroll
        for (int i = 0; i < 4; i++)
#pragma unroll
            for (int j = 0; j < 4; j++)
                Ps[(ty + 16 * i) * SMPAD + tx + 16 * j] = s[i][j] * scale + am[tx + 16 * j];
        __syncthreads();

#pragma unroll
        for (int it = 0; it < 4; it++) {
            int idx = tid + it * 256;
            int row = idx >> 4;
            int d4 = (idx & 15) * 4;
            float4 t = *(const float4*)(v + (size_t)(b * Tz + j0 + row) * Hz + h * HDz + d4);
            Vs[row * SMPAD + d4 + 0] = t.x;
            Vs[row * SMPAD + d4 + 1] = t.y;
            Vs[row * SMPAD + d4 + 2] = t.z;
            Vs[row * SMPAD + d4 + 3] = t.w;
        }
        if (tid < 64) {
            const int row = tid;
            float mo = rm[row];
            float cm = -1e30f;
#pragma unroll 8
            for (int j = 0; j < 64; j++) cm = fmaxf(cm, Ps[row * SMPAD + j]);
            float nm = fmaxf(mo, cm);
            float sc = expf(mo - nm);
            float sum = 0.0f;
#pragma unroll 8
            for (int j = 0; j < 64; j++) {
                float p = expf(Ps[row * SMPAD + j] - nm);
                Ps[row * SMPAD + j] = p;
                sum += p;
            }
            rl[row] = rl[row] * sc + sum;
            rm[row] = nm;
            rs[row] = sc;
        }
        __syncthreads();

#pragma unroll
        for (int i = 0; i < 4; i++) {
            const float sc = rs[ty + 16 * i];
#pragma unroll
            for (int j = 0; j < 4; j++) acc[i][j] *= sc;
        }
#pragma unroll 4
        for (int jj = 0; jj < 64; jj++) {
            float pv[4], vv[4];
#pragma unroll
            for (int i = 0; i < 4; i++) pv[i] = Ps[(ty + 16 * i) * SMPAD + jj];
#pragma unroll
            for (int j = 0; j < 4; j++) vv[j] = Vs[jj * SMPAD + tx + 16 * j];
#pragma unroll
            for (int i = 0; i < 4; i++)
#pragma unroll
                for (int j = 0; j < 4; j++)
                    acc[i][j] = fmaf(pv[i], vv[j], acc[i][j]);
        }
        __syncthreads();
    }

#pragma unroll
    for (int i = 0; i < 4; i++) {
        const float inv = 1.0f / rl[ty + 16 * i];
#pragma unroll
        for (int j = 0; j < 4; j++) {
            size_t off = (size_t)(b * Tz + i0 + ty + 16 * i) * Hz + h * HDz + tx + 16 * j;
            float val = acc[i][j] * inv;
            __nv_bfloat16 hv, lv;
            split1(val, hv, lv);
            ctx_h[off] = hv;
            ctx_l[off] = lv;
        }
    }
}

// ---------------- residual + LayerNorm (fp32 + split out) ----------------
__device__ __forceinline__ float block_reduce_sum(float val, float* red) {
    const int lane = threadIdx.x & 31, w = threadIdx.x >> 5;
#pragma unroll
    for (int o = 16; o > 0; o >>= 1) val += __shfl_down_sync(0xffffffffu, val, o);
    if (lane == 0) red[w] = val;
    __syncthreads();
    if (w == 0) {
        float t = (lane < 8) ? red[lane] : 0.0f;
#pragma unroll
        for (int o = 4; o > 0; o >>= 1) t += __shfl_down_sync(0xffffffffu, t, o);
        if (lane == 0) red[0] = t;
    }
    __syncthreads();
    float r = red[0];
    __syncthreads();
    return r;
}

__global__ __launch_bounds__(256) void ln_kernel(
    const float* __restrict__ a, const float* __restrict__ res,
    const float* __restrict__ g, const float* __restrict__ bb,
    float* __restrict__ out,
    __nv_bfloat16* __restrict__ oh, __nv_bfloat16* __restrict__ ol)
{
    __shared__ float buf[Hz];
    __shared__ float red[32];
    const int row = blockIdx.x;
    const float* ap = a + (size_t)row * Hz;
    const float* rp = res + (size_t)row * Hz;

    float ls = 0.0f;
    for (int i = threadIdx.x; i < Hz; i += 256) {
        float vv = ap[i] + rp[i];
        buf[i] = vv;
        ls += vv;
    }
    const float mean = block_reduce_sum(ls, red) * (1.0f / Hz);

    float lq = 0.0f;
    for (int i = threadIdx.x; i < Hz; i += 256) {
        float d = buf[i] - mean;
        lq += d * d;
    }
    const float var = block_reduce_sum(lq, red) * (1.0f / Hz);
    const float rstd = rsqrtf(var + 1e-12f);

    for (int i = threadIdx.x; i < Hz; i += 256) {
        float y = (buf[i] - mean) * rstd * g[i] + bb[i];
        out[(size_t)row * Hz + i] = y;
        __nv_bfloat16 hv, lv;
        split1(y, hv, lv);
        oh[(size_t)row * Hz + i] = hv;
        ol[(size_t)row * Hz + i] = lv;
    }
}

// ---------------- launch ----------------
extern "C" void kernel_launch(void* const* d_in, const int* in_sizes, int n_in,
                              void* d_out, int out_size)
{
    const float* hidden = (const float*)d_in[0];
    const float* mask   = (const float*)d_in[1];
    const float* Wq  = (const float*)d_in[2];   const float* bq  = (const float*)d_in[3];
    const float* Wk  = (const float*)d_in[4];   const float* bk  = (const float*)d_in[5];
    const float* Wv  = (const float*)d_in[6];   const float* bv  = (const float*)d_in[7];
    const float* Wao = (const float*)d_in[8];   const float* bao = (const float*)d_in[9];
    const float* g1  = (const float*)d_in[10];  const float* b1  = (const float*)d_in[11];
    const float* Wi  = (const float*)d_in[12];  const float* bi  = (const float*)d_in[13];
    const float* Wo  = (const float*)d_in[14];  const float* bo  = (const float*)d_in[15];
    const float* g2  = (const float*)d_in[16];  const float* b2  = (const float*)d_in[17];
    float* out = (float*)d_out;

    float *q, *k, *v, *proj, *attn, *xb;
    cudaGetSymbolAddress((void**)&q,    g_q);
    cudaGetSymbolAddress((void**)&k,    g_k);
    cudaGetSymbolAddress((void**)&v,    g_v);
    cudaGetSymbolAddress((void**)&proj, g_proj);
    cudaGetSymbolAddress((void**)&attn, g_attn);
    cudaGetSymbolAddress((void**)&xb,   g_x);

    __nv_bfloat16 *xh, *xl, *ath, *atl, *cth, *ctl, *ffh, *ffl;
    cudaGetSymbolAddress((void**)&xh,  g_x_h);   cudaGetSymbolAddress((void**)&xl,  g_x_l);
    cudaGetSymbolAddress((void**)&ath, g_attn_h);cudaGetSymbolAddress((void**)&atl, g_attn_l);
    cudaGetSymbolAddress((void**)&cth, g_ctx_h); cudaGetSymbolAddress((void**)&ctl, g_ctx_l);
    cudaGetSymbolAddress((void**)&ffh, g_ff_h);  cudaGetSymbolAddress((void**)&ffl, g_ff_l);

    __nv_bfloat16 *wqh, *wql, *wkh, *wkl, *wvh, *wvl, *waoh, *waol, *wih, *wil, *woh, *wol;
    cudaGetSymbolAddress((void**)&wqh,  g_wq_h);  cudaGetSymbolAddress((void**)&wql,  g_wq_l);
    cudaGetSymbolAddress((void**)&wkh,  g_wk_h);  cudaGetSymbolAddress((void**)&wkl,  g_wk_l);
    cudaGetSymbolAddress((void**)&wvh,  g_wv_h);  cudaGetSymbolAddress((void**)&wvl,  g_wv_l);
    cudaGetSymbolAddress((void**)&waoh, g_wao_h); cudaGetSymbolAddress((void**)&waol, g_wao_l);
    cudaGetSymbolAddress((void**)&wih,  g_wi_h);  cudaGetSymbolAddress((void**)&wil,  g_wi_l);
    cudaGetSymbolAddress((void**)&woh,  g_wo_h);  cudaGetSymbolAddress((void**)&wol,  g_wo_l);

    // pre-split weights + input (once per launch; deterministic)
    const int nHH = Lz * Hz * Hz, nHF = Lz * Hz * FFz, nX = Mz * Hz;
    split_kernel<<<nHH / 1024, 256>>>(Wq,  wqh,  wql,  nHH / 4);
    split_kernel<<<nHH / 1024, 256>>>(Wk,  wkh,  wkl,  nHH / 4);
    split_kernel<<<nHH / 1024, 256>>>(Wv,  wvh,  wvl,  nHH / 4);
    split_kernel<<<nHH / 1024, 256>>>(Wao, waoh, waol, nHH / 4);
    split_kernel<<<nHF / 1024, 256>>>(Wi,  wih,  wil,  nHF / 4);
    split_kernel<<<nHF / 1024, 256>>>(Wo,  woh,  wol,  nHF / 4);
    split_kernel<<<nX  / 1024, 256>>>(hidden, xh, xl, nX / 4);

    const size_t att_smem  = (size_t)(4 * 64 * SMPAD + 4 * 64) * sizeof(float);
    const size_t gemm_smem = (size_t)STG * 2 * (BM * ALD + BKg * BLD) * sizeof(__nv_bfloat16);
    cudaFuncSetAttribute(attention_kernel,
                         cudaFuncAttributeMaxDynamicSharedMemorySize, (int)att_smem);
    cudaFuncSetAttribute(gemm_bf16x3<0>,
                         cudaFuncAttributeMaxDynamicSharedMemorySize, (int)gemm_smem);
    cudaFuncSetAttribute(gemm_bf16x3<1>,
                         cudaFuncAttributeMaxDynamicSharedMemorySize, (int)gemm_smem);

    dim3 gAtt(Tz / 64, Bz * NHz);
    dim3 blkA(16, 16);

    for (int l = 0; l < Lz; l++) {
        const float* xres = (l == 0) ? hidden : xb;
        const size_t oHH = (size_t)l * Hz * Hz;
        const size_t oHF = (size_t)l * Hz * FFz;
        const size_t oH  = (size_t)l * Hz;
        const size_t oF  = (size_t)l * FFz;

        {   // fused QKV
            GemmArgs P = {};
            P.Ah = xh; P.Al = xl;
            P.Bh[0] = wqh + oHH; P.Bl[0] = wql + oHH;
            P.Bh[1] = wkh + oHH; P.Bl[1] = wkl + oHH;
            P.Bh[2] = wvh + oHH; P.Bl[2] = wvl + oHH;
            P.bias[0] = bq + oH; P.bias[1] = bk + oH; P.bias[2] = bv + oH;
            P.C[0] = q; P.C[1] = k; P.C[2] = v;
            gemm_bf16x3<0><<<dim3(Hz / BN, Mz / BM, 3), 256, gemm_smem>>>(P, Hz, Hz);
        }

        attention_kernel<<<gAtt, blkA, att_smem>>>(q, k, v, mask, cth, ctl);

        {   // attention output projection
            GemmArgs P = {};
            P.Ah = cth; P.Al = ctl;
            P.Bh[0] = waoh + oHH; P.Bl[0] = waol + oHH;
            P.bias[0] = bao + oH;
            P.C[0] = proj;
            gemm_bf16x3<0><<<dim3(Hz / BN, Mz / BM, 1), 256, gemm_smem>>>(P, Hz, Hz);
        }
        ln_kernel<<<Mz, 256>>>(proj, xres, g1 + oH, b1 + oH, attn, ath, atl);

        {   // FF1 + GELU (split output)
            GemmArgs P = {};
            P.Ah = ath; P.Al = atl;
            P.Bh[0] = wih + oHF; P.Bl[0] = wil + oHF;
            P.bias[0] = bi + oF;
            P.Ch = ffh; P.Cl = ffl;
            gemm_bf16x3<1><<<dim3(FFz / BN, Mz / BM, 1), 256, gemm_smem>>>(P, Hz, FFz);
        }
        {   // FF2
            GemmArgs P = {};
            P.Ah = ffh; P.Al = ffl;
            P.Bh[0] = woh + oHF; P.Bl[0] = wol + oHF;
            P.bias[0] = bo + oH;
            P.C[0] = proj;
            gemm_bf16x3<0><<<dim3(Hz / BN, Mz / BM, 1), 256, gemm_smem>>>(P, FFz, Hz);
        }
        ln_kernel<<<Mz, 256>>>(proj, attn, g2 + oH, b2 + oH,
                               (l == Lz - 1) ? out : xb, xh, xl);
    }
}

// round 5
// speedup vs baseline: 2.6990x; 1.2468x over previous
#include <cuda_runtime.h>
#include <cuda_bf16.h>
#include <math.h>
#include <stdint.h>

#define Bz  8
#define Tz  512
#define Hz  768
#define NHz 12
#define HDz 64
#define FFz 3072
#define Lz  12
#define Mz  (Bz*Tz)   // 4096

// ---------------- fp32 scratch ----------------
__device__ float g_q[Mz*Hz];
__device__ float g_k[Mz*Hz];
__device__ float g_v[Mz*Hz];
__device__ float g_proj[Mz*Hz];
__device__ float g_attn[Mz*Hz];
__device__ float g_x[Mz*Hz];

// ---------------- split (hi/lo bf16) activation scratch ----------------
__device__ __nv_bfloat16 g_x_h[Mz*Hz],    g_x_l[Mz*Hz];
__device__ __nv_bfloat16 g_attn_h[Mz*Hz], g_attn_l[Mz*Hz];
__device__ __nv_bfloat16 g_ctx_h[Mz*Hz],  g_ctx_l[Mz*Hz];
__device__ __nv_bfloat16 g_ff_h[Mz*FFz],  g_ff_l[Mz*FFz];

// ---------------- split weight storage ([L][K][N], hi/lo) ----------------
__device__ __nv_bfloat16 g_wq_h[Lz*Hz*Hz],  g_wq_l[Lz*Hz*Hz];
__device__ __nv_bfloat16 g_wk_h[Lz*Hz*Hz],  g_wk_l[Lz*Hz*Hz];
__device__ __nv_bfloat16 g_wv_h[Lz*Hz*Hz],  g_wv_l[Lz*Hz*Hz];
__device__ __nv_bfloat16 g_wao_h[Lz*Hz*Hz], g_wao_l[Lz*Hz*Hz];
__device__ __nv_bfloat16 g_wi_h[Lz*Hz*FFz], g_wi_l[Lz*Hz*FFz];
__device__ __nv_bfloat16 g_wo_h[Lz*Hz*FFz], g_wo_l[Lz*Hz*FFz];

// ---------------- helpers ----------------
__device__ __forceinline__ void split1(float x, __nv_bfloat16& h, __nv_bfloat16& l) {
    h = __float2bfloat16(x);
    l = __float2bfloat16(x - __bfloat162float(h));
}
__device__ __forceinline__ void split2(float x, float y, uint32_t& hi, uint32_t& lo) {
    __nv_bfloat16 xh, xl, yh, yl;
    split1(x, xh, xl); split1(y, yh, yl);
    hi = (uint32_t)__bfloat16_as_ushort(xh) | ((uint32_t)__bfloat16_as_ushort(yh) << 16);
    lo = (uint32_t)__bfloat16_as_ushort(xl) | ((uint32_t)__bfloat16_as_ushort(yl) << 16);
}

__global__ __launch_bounds__(256) void split_kernel(
    const float* __restrict__ in, __nv_bfloat16* __restrict__ h,
    __nv_bfloat16* __restrict__ l, int n4)
{
    int i = blockIdx.x * 256 + threadIdx.x;
    if (i >= n4) return;
    float4 v = ((const float4*)in)[i];
    uint32_t h01, l01, h23, l23;
    split2(v.x, v.y, h01, l01);
    split2(v.z, v.w, h23, l23);
    ((uint2*)h)[i] = make_uint2(h01, h23);
    ((uint2*)l)[i] = make_uint2(l01, l23);
}

// ================= bf16x3 mma.sync GEMM (BK=32, 2 CTAs/SM) =================
#define BM 128
#define BN 128
#define BK2 32
#define ALD 40    // 80B rows: conflict-free ldmatrix (r*20 mod 32 distinct per 8)
#define BLD 136   // 272B rows: conflict-free ldmatrix.trans

// element offsets in dynamic smem (bf16)
#define A_ELEMS (2*2*BM*ALD)      // 20480
#define ASOFF(s,pl,m,k)  ((((s)*2+(pl))*BM + (m))*ALD + (k))
#define BSOFF(s,pl,kk,n) (A_ELEMS + (((s)*2+(pl))*BK2 + (kk))*BLD + (n))
#define GEMM_SMEM ((A_ELEMS + 2*2*BK2*BLD) * 2)   // bytes = 75776

struct GemmArgs {
    const __nv_bfloat16 *Ah, *Al;
    const __nv_bfloat16 *Bh[3], *Bl[3];
    const float* bias[3];
    float* C[3];
    __nv_bfloat16 *Ch, *Cl;
};

__device__ __forceinline__ void cpa16(void* dst, const void* src) {
    uint32_t d = (uint32_t)__cvta_generic_to_shared(dst);
    asm volatile("cp.async.cg.shared.global [%0], [%1], 16;" :: "r"(d), "l"(src));
}
__device__ __forceinline__ void ldsm4(uint32_t* r, const void* p) {
    uint32_t a = (uint32_t)__cvta_generic_to_shared(p);
    asm volatile("ldmatrix.sync.aligned.m8n8.x4.shared.b16 {%0,%1,%2,%3}, [%4];"
                 : "=r"(r[0]), "=r"(r[1]), "=r"(r[2]), "=r"(r[3]) : "r"(a));
}
__device__ __forceinline__ void ldsm4t(uint32_t* r, const void* p) {
    uint32_t a = (uint32_t)__cvta_generic_to_shared(p);
    asm volatile("ldmatrix.sync.aligned.m8n8.x4.trans.shared.b16 {%0,%1,%2,%3}, [%4];"
                 : "=r"(r[0]), "=r"(r[1]), "=r"(r[2]), "=r"(r[3]) : "r"(a));
}
__device__ __forceinline__ void mma16816(float* c, const uint32_t* a, const uint32_t* b) {
    asm volatile(
        "mma.sync.aligned.m16n8k16.row.col.f32.bf16.bf16.f32 "
        "{%0,%1,%2,%3}, {%4,%5,%6,%7}, {%8,%9}, {%0,%1,%2,%3};"
        : "+f"(c[0]), "+f"(c[1]), "+f"(c[2]), "+f"(c[3])
        : "r"(a[0]), "r"(a[1]), "r"(a[2]), "r"(a[3]), "r"(b[0]), "r"(b[1]));
}

// MODE 0: fp32 out (+bias). MODE 1: bias + exact GELU, split bf16 out.
template<int MODE>
__global__ __launch_bounds__(256, 2) void gemm_bf16x3(GemmArgs P, int K, int N)
{
    extern __shared__ __align__(16) __nv_bfloat16 sm[];

    const int z = blockIdx.z;
    const __nv_bfloat16* __restrict__ Ah = P.Ah;
    const __nv_bfloat16* __restrict__ Al = P.Al;
    const __nv_bfloat16* __restrict__ Bh = P.Bh[z];
    const __nv_bfloat16* __restrict__ Bl = P.Bl[z];
    const float* __restrict__ bias = P.bias[z];

    const int n0 = blockIdx.x * BN;
    const int m0 = blockIdx.y * BM;
    const int tid  = threadIdx.x;
    const int lane = tid & 31;
    const int warp = tid >> 5;
    const int warpM = warp >> 2;   // 0..1
    const int warpN = warp & 3;    // 0..3

    const int nT = K / BK2;

    auto issue = [&](int t, int s) {
        const int k0 = t * BK2;
#pragma unroll
        for (int p = 0; p < 2; p++) {
            const int idx = tid + p * 256;
            const int ar = idx >> 2, ac = (idx & 3) * 8;       // 128 rows x 32 cols
            cpa16(sm + ASOFF(s, 0, ar, ac), Ah + (size_t)(m0 + ar) * K + k0 + ac);
            cpa16(sm + ASOFF(s, 1, ar, ac), Al + (size_t)(m0 + ar) * K + k0 + ac);
            const int br = idx >> 4, bc = (idx & 15) * 8;      // 32 rows x 128 cols
            cpa16(sm + BSOFF(s, 0, br, bc), Bh + (size_t)(k0 + br) * N + n0 + bc);
            cpa16(sm + BSOFF(s, 1, br, bc), Bl + (size_t)(k0 + br) * N + n0 + bc);
        }
        asm volatile("cp.async.commit_group;" ::: "memory");
    };

    issue(0, 0);
    issue(1, 1);

    float acc[4][4][4] = {};

    for (int t = 0; t < nT; t++) {
        if (t + 1 < nT) asm volatile("cp.async.wait_group 1;" ::: "memory");
        else            asm volatile("cp.async.wait_group 0;" ::: "memory");
        __syncthreads();
        const int s = t & 1;

#pragma unroll
        for (int sub = 0; sub < 2; sub++) {
            uint32_t ah[4][4], al[4][4], bh[4][2], bl[4][2];
            const int arow = warpM * 64 + (lane & 15);
            const int acol = sub * 16 + (lane >> 4) * 8;
#pragma unroll
            for (int mi = 0; mi < 4; mi++) {
                ldsm4(ah[mi], sm + ASOFF(s, 0, arow + mi * 16, acol));
                ldsm4(al[mi], sm + ASOFF(s, 1, arow + mi * 16, acol));
            }
            const int brow = sub * 16 + (lane & 15);
#pragma unroll
            for (int pr = 0; pr < 2; pr++) {
                const int bcol = warpN * 32 + pr * 16 + (lane >> 4) * 8;
                uint32_t tmp[4];
                ldsm4t(tmp, sm + BSOFF(s, 0, brow, bcol));
                bh[pr * 2][0] = tmp[0]; bh[pr * 2][1] = tmp[1];
                bh[pr * 2 + 1][0] = tmp[2]; bh[pr * 2 + 1][1] = tmp[3];
                ldsm4t(tmp, sm + BSOFF(s, 1, brow, bcol));
                bl[pr * 2][0] = tmp[0]; bl[pr * 2][1] = tmp[1];
                bl[pr * 2 + 1][0] = tmp[2]; bl[pr * 2 + 1][1] = tmp[3];
            }
#pragma unroll
            for (int mi = 0; mi < 4; mi++)
#pragma unroll
                for (int ni = 0; ni < 4; ni++) {
                    mma16816(acc[mi][ni], ah[mi], bh[ni]);
                    mma16816(acc[mi][ni], ah[mi], bl[ni]);
                    mma16816(acc[mi][ni], al[mi], bh[ni]);
                }
        }
        __syncthreads();
        if (t + 2 < nT) issue(t + 2, s);
    }

    // epilogue
    const int g  = lane >> 2;
    const int tg = lane & 3;
#pragma unroll
    for (int mi = 0; mi < 4; mi++) {
#pragma unroll
        for (int ni = 0; ni < 4; ni++) {
            const int row = m0 + warpM * 64 + mi * 16 + g;
            const int col = n0 + warpN * 32 + ni * 8 + tg * 2;
            const float b0 = bias[col], b1 = bias[col + 1];
            float v0 = acc[mi][ni][0] + b0;
            float v1 = acc[mi][ni][1] + b1;
            float v2 = acc[mi][ni][2] + b0;
            float v3 = acc[mi][ni][3] + b1;
            if (MODE == 1) {
                v0 = 0.5f * v0 * (1.0f + erff(v0 * 0.70710678118654752f));
                v1 = 0.5f * v1 * (1.0f + erff(v1 * 0.70710678118654752f));
                v2 = 0.5f * v2 * (1.0f + erff(v2 * 0.70710678118654752f));
                v3 = 0.5f * v3 * (1.0f + erff(v3 * 0.70710678118654752f));
                uint32_t hw, lw;
                split2(v0, v1, hw, lw);
                *(uint32_t*)(P.Ch + (size_t)row * N + col) = hw;
                *(uint32_t*)(P.Cl + (size_t)row * N + col) = lw;
                split2(v2, v3, hw, lw);
                *(uint32_t*)(P.Ch + (size_t)(row + 8) * N + col) = hw;
                *(uint32_t*)(P.Cl + (size_t)(row + 8) * N + col) = lw;
            } else {
                float* C = P.C[z];
                *(float2*)(C + (size_t)row * N + col)       = make_float2(v0, v1);
                *(float2*)(C + (size_t)(row + 8) * N + col) = make_float2(v2, v3);
            }
        }
    }
}

// ---------------- fused attention (flash-style, fp32; split bf16 out) ----------------
#define SMPAD 65
__global__ __launch_bounds__(256) void attention_kernel(
    const float* __restrict__ q, const float* __restrict__ k,
    const float* __restrict__ v, const float* __restrict__ mask,
    __nv_bfloat16* __restrict__ ctx_h, __nv_bfloat16* __restrict__ ctx_l)
{
    extern __shared__ float smf[];
    float* Qs = smf;
    float* Ks = Qs + 64 * SMPAD;
    float* Vs = Ks + 64 * SMPAD;
    float* Ps = Vs + 64 * SMPAD;
    float* rm = Ps + 64 * SMPAD;
    float* rl = rm + 64;
    float* rs = rl + 64;
    float* am = rs + 64;

    const int tx = threadIdx.x, ty = threadIdx.y;
    const int tid = ty * 16 + tx;
    const int bh = blockIdx.y;
    const int b = bh / NHz, h = bh % NHz;
    const int i0 = blockIdx.x * 64;
    const float scale = 0.125f;

#pragma unroll
    for (int it = 0; it < 4; it++) {
        int idx = tid + it * 256;
        int row = idx >> 4;
        int d4 = (idx & 15) * 4;
        float4 t = *(const float4*)(q + (size_t)(b * Tz + i0 + row) * Hz + h * HDz + d4);
        Qs[row * SMPAD + d4 + 0] = t.x;
        Qs[row * SMPAD + d4 + 1] = t.y;
        Qs[row * SMPAD + d4 + 2] = t.z;
        Qs[row * SMPAD + d4 + 3] = t.w;
    }
    if (tid < 64) { rm[tid] = -1e30f; rl[tid] = 0.0f; }

    float acc[4][4] = {};

    for (int jc = 0; jc < Tz / 64; jc++) {
        const int j0 = jc * 64;
#pragma unroll
        for (int it = 0; it < 4; it++) {
            int idx = tid + it * 256;
            int row = idx >> 4;
            int d4 = (idx & 15) * 4;
            float4 t = *(const float4*)(k + (size_t)(b * Tz + j0 + row) * Hz + h * HDz + d4);
            Ks[row * SMPAD + d4 + 0] = t.x;
            Ks[row * SMPAD + d4 + 1] = t.y;
            Ks[row * SMPAD + d4 + 2] = t.z;
            Ks[row * SMPAD + d4 + 3] = t.w;
        }
        if (tid < 64) am[tid] = (1.0f - mask[b * Tz + j0 + tid]) * -10000.0f;
        __syncthreads();

        float s[4][4] = {};
#pragma unroll 4
        for (int d = 0; d < 64; d++) {
            float qv[4], kv[4];
#pragma unroll
            for (int i = 0; i < 4; i++) qv[i] = Qs[(ty + 16 * i) * SMPAD + d];
#pragma unroll
            for (int j = 0; j < 4; j++) kv[j] = Ks[(tx + 16 * j) * SMPAD + d];
#pragma unroll
            for (int i = 0; i < 4; i++)
#pragma unroll
                for (int j = 0; j < 4; j++)
                    s[i][j] = fmaf(qv[i], kv[j], s[i][j]);
        }
#pragma unroll
        for (int i = 0; i < 4; i++)
#pragma unroll
            for (int j = 0; j < 4; j++)
                Ps[(ty + 16 * i) * SMPAD + tx + 16 * j] = s[i][j] * scale + am[tx + 16 * j];
        __syncthreads();

#pragma unroll
        for (int it = 0; it < 4; it++) {
            int idx = tid + it * 256;
            int row = idx >> 4;
            int d4 = (idx & 15) * 4;
            float4 t = *(const float4*)(v + (size_t)(b * Tz + j0 + row) * Hz + h * HDz + d4);
            Vs[row * SMPAD + d4 + 0] = t.x;
            Vs[row * SMPAD + d4 + 1] = t.y;
            Vs[row * SMPAD + d4 + 2] = t.z;
            Vs[row * SMPAD + d4 + 3] = t.w;
        }
        if (tid < 64) {
            const int row = tid;
            float mo = rm[row];
            float cm = -1e30f;
#pragma unroll 8
            for (int j = 0; j < 64; j++) cm = fmaxf(cm, Ps[row * SMPAD + j]);
            float nm = fmaxf(mo, cm);
            float sc = expf(mo - nm);
            float sum = 0.0f;
#pragma unroll 8
            for (int j = 0; j < 64; j++) {
                float p = expf(Ps[row * SMPAD + j] - nm);
                Ps[row * SMPAD + j] = p;
                sum += p;
            }
            rl[row] = rl[row] * sc + sum;
            rm[row] = nm;
            rs[row] = sc;
        }
        __syncthreads();

#pragma unroll
        for (int i = 0; i < 4; i++) {
            const float sc = rs[ty + 16 * i];
#pragma unroll
            for (int j = 0; j < 4; j++) acc[i][j] *= sc;
        }
#pragma unroll 4
        for (int jj = 0; jj < 64; jj++) {
            float pv[4], vv[4];
#pragma unroll
            for (int i = 0; i < 4; i++) pv[i] = Ps[(ty + 16 * i) * SMPAD + jj];
#pragma unroll
            for (int j = 0; j < 4; j++) vv[j] = Vs[jj * SMPAD + tx + 16 * j];
#pragma unroll
            for (int i = 0; i < 4; i++)
#pragma unroll
                for (int j = 0; j < 4; j++)
                    acc[i][j] = fmaf(pv[i], vv[j], acc[i][j]);
        }
        __syncthreads();
    }

#pragma unroll
    for (int i = 0; i < 4; i++) {
        const float inv = 1.0f / rl[ty + 16 * i];
#pragma unroll
        for (int j = 0; j < 4; j++) {
            size_t off = (size_t)(b * Tz + i0 + ty + 16 * i) * Hz + h * HDz + tx + 16 * j;
            float val = acc[i][j] * inv;
            __nv_bfloat16 hv, lv;
            split1(val, hv, lv);
            ctx_h[off] = hv;
            ctx_l[off] = lv;
        }
    }
}

// ---------------- residual + LayerNorm (fp32 + split out) ----------------
__device__ __forceinline__ float block_reduce_sum(float val, float* red) {
    const int lane = threadIdx.x & 31, w = threadIdx.x >> 5;
#pragma unroll
    for (int o = 16; o > 0; o >>= 1) val += __shfl_down_sync(0xffffffffu, val, o);
    if (lane == 0) red[w] = val;
    __syncthreads();
    if (w == 0) {
        float t = (lane < 8) ? red[lane] : 0.0f;
#pragma unroll
        for (int o = 4; o > 0; o >>= 1) t += __shfl_down_sync(0xffffffffu, t, o);
        if (lane == 0) red[0] = t;
    }
    __syncthreads();
    float r = red[0];
    __syncthreads();
    return r;
}

__global__ __launch_bounds__(256) void ln_kernel(
    const float* __restrict__ a, const float* __restrict__ res,
    const float* __restrict__ g, const float* __restrict__ bb,
    float* __restrict__ out,
    __nv_bfloat16* __restrict__ oh, __nv_bfloat16* __restrict__ ol)
{
    __shared__ float buf[Hz];
    __shared__ float red[32];
    const int row = blockIdx.x;
    const float* ap = a + (size_t)row * Hz;
    const float* rp = res + (size_t)row * Hz;

    float ls = 0.0f;
    for (int i = threadIdx.x; i < Hz; i += 256) {
        float vv = ap[i] + rp[i];
        buf[i] = vv;
        ls += vv;
    }
    const float mean = block_reduce_sum(ls, red) * (1.0f / Hz);

    float lq = 0.0f;
    for (int i = threadIdx.x; i < Hz; i += 256) {
        float d = buf[i] - mean;
        lq += d * d;
    }
    const float var = block_reduce_sum(lq, red) * (1.0f / Hz);
    const float rstd = rsqrtf(var + 1e-12f);

    for (int i = threadIdx.x; i < Hz; i += 256) {
        float y = (buf[i] - mean) * rstd * g[i] + bb[i];
        out[(size_t)row * Hz + i] = y;
        __nv_bfloat16 hv, lv;
        split1(y, hv, lv);
        oh[(size_t)row * Hz + i] = hv;
        ol[(size_t)row * Hz + i] = lv;
    }
}

// ---------------- launch ----------------
extern "C" void kernel_launch(void* const* d_in, const int* in_sizes, int n_in,
                              void* d_out, int out_size)
{
    const float* hidden = (const float*)d_in[0];
    const float* mask   = (const float*)d_in[1];
    const float* Wq  = (const float*)d_in[2];   const float* bq  = (const float*)d_in[3];
    const float* Wk  = (const float*)d_in[4];   const float* bk  = (const float*)d_in[5];
    const float* Wv  = (const float*)d_in[6];   const float* bv  = (const float*)d_in[7];
    const float* Wao = (const float*)d_in[8];   const float* bao = (const float*)d_in[9];
    const float* g1  = (const float*)d_in[10];  const float* b1  = (const float*)d_in[11];
    const float* Wi  = (const float*)d_in[12];  const float* bi  = (const float*)d_in[13];
    const float* Wo  = (const float*)d_in[14];  const float* bo  = (const float*)d_in[15];
    const float* g2  = (const float*)d_in[16];  const float* b2  = (const float*)d_in[17];
    float* out = (float*)d_out;

    float *q, *k, *v, *proj, *attn, *xb;
    cudaGetSymbolAddress((void**)&q,    g_q);
    cudaGetSymbolAddress((void**)&k,    g_k);
    cudaGetSymbolAddress((void**)&v,    g_v);
    cudaGetSymbolAddress((void**)&proj, g_proj);
    cudaGetSymbolAddress((void**)&attn, g_attn);
    cudaGetSymbolAddress((void**)&xb,   g_x);

    __nv_bfloat16 *xh, *xl, *ath, *atl, *cth, *ctl, *ffh, *ffl;
    cudaGetSymbolAddress((void**)&xh,  g_x_h);    cudaGetSymbolAddress((void**)&xl,  g_x_l);
    cudaGetSymbolAddress((void**)&ath, g_attn_h); cudaGetSymbolAddress((void**)&atl, g_attn_l);
    cudaGetSymbolAddress((void**)&cth, g_ctx_h);  cudaGetSymbolAddress((void**)&ctl, g_ctx_l);
    cudaGetSymbolAddress((void**)&ffh, g_ff_h);   cudaGetSymbolAddress((void**)&ffl, g_ff_l);

    __nv_bfloat16 *wqh, *wql, *wkh, *wkl, *wvh, *wvl, *waoh, *waol, *wih, *wil, *woh, *wol;
    cudaGetSymbolAddress((void**)&wqh,  g_wq_h);  cudaGetSymbolAddress((void**)&wql,  g_wq_l);
    cudaGetSymbolAddress((void**)&wkh,  g_wk_h);  cudaGetSymbolAddress((void**)&wkl,  g_wk_l);
    cudaGetSymbolAddress((void**)&wvh,  g_wv_h);  cudaGetSymbolAddress((void**)&wvl,  g_wv_l);
    cudaGetSymbolAddress((void**)&waoh, g_wao_h); cudaGetSymbolAddress((void**)&waol, g_wao_l);
    cudaGetSymbolAddress((void**)&wih,  g_wi_h);  cudaGetSymbolAddress((void**)&wil,  g_wi_l);
    cudaGetSymbolAddress((void**)&woh,  g_wo_h);  cudaGetSymbolAddress((void**)&wol,  g_wo_l);

    // pre-split weights + input
    const int nHH = Lz * Hz * Hz, nHF = Lz * Hz * FFz, nX = Mz * Hz;
    split_kernel<<<nHH / 1024, 256>>>(Wq,  wqh,  wql,  nHH / 4);
    split_kernel<<<nHH / 1024, 256>>>(Wk,  wkh,  wkl,  nHH / 4);
    split_kernel<<<nHH / 1024, 256>>>(Wv,  wvh,  wvl,  nHH / 4);
    split_kernel<<<nHH / 1024, 256>>>(Wao, waoh, waol, nHH / 4);
    split_kernel<<<nHF / 1024, 256>>>(Wi,  wih,  wil,  nHF / 4);
    split_kernel<<<nHF / 1024, 256>>>(Wo,  woh,  wol,  nHF / 4);
    split_kernel<<<nX  / 1024, 256>>>(hidden, xh, xl, nX / 4);

    const size_t att_smem  = (size_t)(4 * 64 * SMPAD + 4 * 64) * sizeof(float);
    cudaFuncSetAttribute(attention_kernel,
                         cudaFuncAttributeMaxDynamicSharedMemorySize, (int)att_smem);
    cudaFuncSetAttribute(gemm_bf16x3<0>,
                         cudaFuncAttributeMaxDynamicSharedMemorySize, GEMM_SMEM);
    cudaFuncSetAttribute(gemm_bf16x3<1>,
                         cudaFuncAttributeMaxDynamicSharedMemorySize, GEMM_SMEM);

    dim3 gAtt(Tz / 64, Bz * NHz);
    dim3 blkA(16, 16);

    for (int l = 0; l < Lz; l++) {
        const float* xres = (l == 0) ? hidden : xb;
        const size_t oHH = (size_t)l * Hz * Hz;
        const size_t oHF = (size_t)l * Hz * FFz;
        const size_t oH  = (size_t)l * Hz;
        const size_t oF  = (size_t)l * FFz;

        {   // fused QKV
            GemmArgs P = {};
            P.Ah = xh; P.Al = xl;
            P.Bh[0] = wqh + oHH; P.Bl[0] = wql + oHH;
            P.Bh[1] = wkh + oHH; P.Bl[1] = wkl + oHH;
            P.Bh[2] = wvh + oHH; P.Bl[2] = wvl + oHH;
            P.bias[0] = bq + oH; P.bias[1] = bk + oH; P.bias[2] = bv + oH;
            P.C[0] = q; P.C[1] = k; P.C[2] = v;
            gemm_bf16x3<0><<<dim3(Hz / BN, Mz / BM, 3), 256, GEMM_SMEM>>>(P, Hz, Hz);
        }

        attention_kernel<<<gAtt, blkA, att_smem>>>(q, k, v, mask, cth, ctl);

        {   // attention output projection
            GemmArgs P = {};
            P.Ah = cth; P.Al = ctl;
            P.Bh[0] = waoh + oHH; P.Bl[0] = waol + oHH;
            P.bias[0] = bao + oH;
            P.C[0] = proj;
            gemm_bf16x3<0><<<dim3(Hz / BN, Mz / BM, 1), 256, GEMM_SMEM>>>(P, Hz, Hz);
        }
        ln_kernel<<<Mz, 256>>>(proj, xres, g1 + oH, b1 + oH, attn, ath, atl);

        {   // FF1 + GELU (split bf16 out)
            GemmArgs P = {};
            P.Ah = ath; P.Al = atl;
            P.Bh[0] = wih + oHF; P.Bl[0] = wil + oHF;
            P.bias[0] = bi + oF;
            P.Ch = ffh; P.Cl = ffl;
            gemm_bf16x3<1><<<dim3(FFz / BN, Mz / BM, 1), 256, GEMM_SMEM>>>(P, Hz, FFz);
        }
        {   // FF2
            GemmArgs P = {};
            P.Ah = ffh; P.Al = ffl;
            P.Bh[0] = woh + oHF; P.Bl[0] = wol + oHF;
            P.bias[0] = bo + oH;
            P.C[0] = proj;
            gemm_bf16x3<0><<<dim3(Hz / BN, Mz / BM, 1), 256, GEMM_SMEM>>>(P, FFz, Hz);
        }
        ln_kernel<<<Mz, 256>>>(proj, attn, g2 + oH, b2 + oH,
                               (l == Lz - 1) ? out : xb, xh, xl);
    }
}